// round 8
// baseline (speedup 1.0000x reference)
#include <cuda_runtime.h>
#include <cuda_bf16.h>
#include <cstdint>

#define ROUNDS 64
#define HID 256
#define BATCH 65536
#define NBW (BATCH / 32)            // 2048 packed batch words
#define BWSET 32                    // bw words per CTA (one per lane)
#define JSPLIT 2
#define JCTA (HID / JSPLIT)         // 128 j per CTA
#define RK_THREADS 512              // 16 warps

// ---------------- device-global scratch (no allocs allowed) ----------------
__device__ uint32_t g_S[2][HID * NBW];          // bit-sliced state [k][bw], ping-pong (2x2MB)
__device__ uint32_t g_Wb[ROUNDS * HID * 8];     // W bits: [r][j][8 words over k]
__device__ uint32_t g_nm[ROUNDS * HID];         // noise masks: 0 or 0xFFFFFFFF

// ---------------- prep: pack |W| bits ----------------
__global__ void pack_W(const float* __restrict__ W) {
    int w = blockIdx.x * blockDim.x + threadIdx.x;      // word index
    if (w >= ROUNDS * HID * 8) return;
    const float* src = W + (size_t)w * 32;              // 32 consecutive k of row (r,j)
    uint32_t bits = 0;
    #pragma unroll
    for (int q = 0; q < 8; ++q) {
        float4 v = reinterpret_cast<const float4*>(src)[q];
        bits |= (v.x != 0.f ? 1u : 0u) << (q * 4 + 0);
        bits |= (v.y != 0.f ? 1u : 0u) << (q * 4 + 1);
        bits |= (v.z != 0.f ? 1u : 0u) << (q * 4 + 2);
        bits |= (v.w != 0.f ? 1u : 0u) << (q * 4 + 3);
    }
    g_Wb[w] = bits;
}

// ---------------- prep: noise -> full masks ----------------
__global__ void pack_noise(const float* __restrict__ noise) {
    int i = blockIdx.x * blockDim.x + threadIdx.x;
    if (i < ROUNDS * HID) g_nm[i] = (noise[i] != 0.f) ? 0xFFFFFFFFu : 0u;
}

// ---------------- prep: bit-slice the state ----------------
// S[k][bw]: bit b = state[bw*32+b][k]
__global__ void pack_state(const float* __restrict__ state) {
    int warp = (blockIdx.x * blockDim.x + threadIdx.x) >> 5;  // one warp per bw
    int lane = threadIdx.x & 31;
    if (warp >= NBW) return;
    const float* base = state + (size_t)warp * 32 * HID;
    #pragma unroll
    for (int kc = 0; kc < 8; ++kc) {
        int k = kc * 32 + lane;
        uint32_t word = 0;
        #pragma unroll
        for (int b = 0; b < 32; ++b)
            word |= (base[(size_t)b * HID + k] != 0.f ? 1u : 0u) << b;
        g_S[0][(size_t)k * NBW + warp] = word;
    }
}

// ---------------- per-round GF(2) kernel ----------------
// grid (64, 2): x = bw-set (32 words), y = j-half (128 j)
// SMEM: LUT[64 chunks][16 entries][32 lanes] (128KB) + wb slice (4KB)
#define LUT_WORDS (64 * 16 * 32)
#define RK_SMEM (LUT_WORDS * 4 + JCTA * 8 * 4)

__global__ void __launch_bounds__(RK_THREADS, 1)
round_gf2(const uint32_t* __restrict__ Sin, uint32_t* __restrict__ Sout,
          const uint32_t* __restrict__ wb, const uint32_t* __restrict__ nmask) {
    extern __shared__ uint32_t sm[];
    uint32_t* lut = sm;                       // [c][e][lane]
    uint32_t* wbs = sm + LUT_WORDS;           // [JCTA][8]

    const int tid  = threadIdx.x;
    const int wid  = tid >> 5;
    const int lane = tid & 31;
    const int bwb  = blockIdx.x * BWSET;
    const int jb   = blockIdx.y * JCTA;

    // stage this CTA's W-bit words (coalesced)
    for (int i = tid; i < JCTA * 8; i += RK_THREADS)
        wbs[i] = wb[jb * 8 + i];

    // build LUT: warp w owns chunks w*4 .. w*4+3 (Gray-code incremental)
    #pragma unroll
    for (int cc = 0; cc < 4; ++cc) {
        int c = wid * 4 + cc;
        const uint32_t* sp = Sin + (size_t)(c * 4) * NBW + bwb + lane;
        uint32_t s0 = sp[0], s1 = sp[NBW], s2 = sp[2 * NBW], s3 = sp[3 * NBW];
        uint32_t* L = lut + c * (16 * 32) + lane;
        uint32_t t = 0;
        L[0 * 32] = t;
        t ^= s0; L[1 * 32] = t;   t ^= s1; L[3 * 32] = t;
        t ^= s0; L[2 * 32] = t;   t ^= s2; L[6 * 32] = t;
        t ^= s0; L[7 * 32] = t;   t ^= s1; L[5 * 32] = t;
        t ^= s0; L[4 * 32] = t;   t ^= s3; L[12 * 32] = t;
        t ^= s0; L[13 * 32] = t;  t ^= s1; L[15 * 32] = t;
        t ^= s0; L[14 * 32] = t;  t ^= s2; L[10 * 32] = t;
        t ^= s0; L[11 * 32] = t;  t ^= s1; L[9 * 32] = t;
        t ^= s0; L[8 * 32] = t;
    }
    __syncthreads();

    // each warp computes 8 output words (j columns) for its 32 bw lanes
    #pragma unroll 1
    for (int jj = 0; jj < 8; ++jj) {
        int jl = wid * 8 + jj;                // local j
        int j  = jb + jl;
        const uint32_t* wd = wbs + jl * 8;
        uint32_t acc0 = 0, acc1 = 0;          // two chains for ILP
        #pragma unroll
        for (int cw = 0; cw < 8; ++cw) {
            uint32_t wword = wd[cw];          // uniform LDS
            #pragma unroll
            for (int n = 0; n < 8; n += 2) {
                int c0 = cw * 8 + n, c1 = c0 + 1;
                uint32_t i0 = (wword >> (n * 4)) & 15u;
                uint32_t i1 = (wword >> (n * 4 + 4)) & 15u;
                acc0 ^= lut[(c0 * 16 + i0) * 32 + lane];
                acc1 ^= lut[(c1 * 16 + i1) * 32 + lane];
            }
        }
        uint32_t r = acc0 ^ acc1 ^ nmask[j];
        Sout[(size_t)j * NBW + bwb + lane] = r;
    }
}

// ---------------- unpack final bits to fp32 ----------------
__global__ void unpack_state(const uint32_t* __restrict__ S, float* __restrict__ out) {
    __shared__ uint32_t smw[HID];
    int bw = blockIdx.x;
    int tid = threadIdx.x;                    // 256 threads
    smw[tid] = S[(size_t)tid * NBW + bw];     // k = tid
    __syncthreads();
    int b  = tid >> 3;                        // row within group (0..31)
    int kq = (tid & 7) * 32;                  // 32 k per thread
    float* dst = out + ((size_t)bw * 32 + b) * HID + kq;
    #pragma unroll
    for (int q = 0; q < 8; ++q) {
        float4 v;
        v.x = (float)((smw[kq + q * 4 + 0] >> b) & 1u);
        v.y = (float)((smw[kq + q * 4 + 1] >> b) & 1u);
        v.z = (float)((smw[kq + q * 4 + 2] >> b) & 1u);
        v.w = (float)((smw[kq + q * 4 + 3] >> b) & 1u);
        reinterpret_cast<float4*>(dst)[q] = v;
    }
}

// ---------------- launch ----------------
extern "C" void kernel_launch(void* const* d_in, const int* in_sizes, int n_in,
                              void* d_out, int out_size) {
    const float* state    = (const float*)d_in[0];   // [65536, 256]
    const float* matrices = (const float*)d_in[1];   // [64, 256, 256]
    const float* noise    = (const float*)d_in[2];   // [64, 256]
    float* out = (float*)d_out;

    pack_W<<<(ROUNDS * HID * 8 + 255) / 256, 256>>>(matrices);
    pack_noise<<<(ROUNDS * HID + 255) / 256, 256>>>(noise);
    pack_state<<<(NBW * 32 + 255) / 256, 256>>>(state);

    static uint32_t* S0 = nullptr;
    uint32_t *s0, *s1;
    cudaGetSymbolAddress((void**)&s0, g_S);          // not an allocation
    s1 = s0 + (size_t)HID * NBW;
    uint32_t* wbp;
    cudaGetSymbolAddress((void**)&wbp, g_Wb);
    uint32_t* nmp;
    cudaGetSymbolAddress((void**)&nmp, g_nm);
    (void)S0;

    cudaFuncSetAttribute(round_gf2, cudaFuncAttributeMaxDynamicSharedMemorySize, RK_SMEM);

    dim3 grid(NBW / BWSET, JSPLIT);
    for (int r = 0; r < ROUNDS; ++r) {
        const uint32_t* in  = (r & 1) ? s1 : s0;
        uint32_t*       dst = (r & 1) ? s0 : s1;
        round_gf2<<<grid, RK_THREADS, RK_SMEM>>>(in, dst, wbp + (size_t)r * HID * 8,
                                                 nmp + (size_t)r * HID);
    }
    // after 64 rounds result is back in s0
    unpack_state<<<NBW, HID>>>(s0, out);
}

// round 9
// speedup vs baseline: 1.0034x; 1.0034x over previous
#include <cuda_runtime.h>
#include <cuda_bf16.h>
#include <cstdint>

#define ROUNDS 64
#define HID 256
#define BATCH 65536
#define NBW (BATCH / 32)            // 2048 packed batch words
#define BWSET 32                    // bw words per CTA (one per lane)
#define JSPLIT 2
#define JCTA (HID / JSPLIT)         // 128 j per CTA
#define RK_THREADS 512              // 16 warps

// ---------------- device-global scratch (no allocs allowed) ----------------
__device__ uint32_t g_S[2][HID * NBW];          // bit-sliced state [k][bw], ping-pong (2x2MB)
__device__ uint32_t g_Wb[ROUNDS * HID * 8];     // W bits: [r][j][8 words over k]
__device__ uint32_t g_nm[ROUNDS * HID];         // noise masks: 0 or 0xFFFFFFFF

// ---------------- prep: pack |W| bits ----------------
__global__ void pack_W(const float* __restrict__ W) {
    int w = blockIdx.x * blockDim.x + threadIdx.x;      // word index
    if (w >= ROUNDS * HID * 8) return;
    const float* src = W + (size_t)w * 32;              // 32 consecutive k of row (r,j)
    uint32_t bits = 0;
    #pragma unroll
    for (int q = 0; q < 8; ++q) {
        float4 v = reinterpret_cast<const float4*>(src)[q];
        bits |= (v.x != 0.f ? 1u : 0u) << (q * 4 + 0);
        bits |= (v.y != 0.f ? 1u : 0u) << (q * 4 + 1);
        bits |= (v.z != 0.f ? 1u : 0u) << (q * 4 + 2);
        bits |= (v.w != 0.f ? 1u : 0u) << (q * 4 + 3);
    }
    g_Wb[w] = bits;
}

// ---------------- prep: noise -> full masks ----------------
__global__ void pack_noise(const float* __restrict__ noise) {
    int i = blockIdx.x * blockDim.x + threadIdx.x;
    if (i < ROUNDS * HID) g_nm[i] = (noise[i] != 0.f) ? 0xFFFFFFFFu : 0u;
}

// ---------------- prep: bit-slice the state ----------------
// S[k][bw]: bit b = state[bw*32+b][k]
__global__ void pack_state(const float* __restrict__ state) {
    int warp = (blockIdx.x * blockDim.x + threadIdx.x) >> 5;  // one warp per bw
    int lane = threadIdx.x & 31;
    if (warp >= NBW) return;
    const float* base = state + (size_t)warp * 32 * HID;
    #pragma unroll
    for (int kc = 0; kc < 8; ++kc) {
        int k = kc * 32 + lane;
        uint32_t word = 0;
        #pragma unroll
        for (int b = 0; b < 32; ++b)
            word |= (base[(size_t)b * HID + k] != 0.f ? 1u : 0u) << b;
        g_S[0][(size_t)k * NBW + warp] = word;
    }
}

// ---------------- per-round GF(2) kernel ----------------
// grid (64, 2): x = bw-set (32 words), y = j-half (128 j)
// SMEM: LUT[64 chunks][16 entries][32 lanes] (128KB) + wb slice (4KB)
#define LUT_WORDS (64 * 16 * 32)
#define RK_SMEM (LUT_WORDS * 4 + JCTA * 8 * 4)

__global__ void __launch_bounds__(RK_THREADS, 1)
round_gf2(const uint32_t* __restrict__ Sin, uint32_t* __restrict__ Sout,
          const uint32_t* __restrict__ wb, const uint32_t* __restrict__ nmask) {
    extern __shared__ uint32_t sm[];
    uint32_t* lut = sm;                       // [c][e][lane]
    uint32_t* wbs = sm + LUT_WORDS;           // [JCTA][8]

    const int tid  = threadIdx.x;
    const int wid  = tid >> 5;
    const int lane = tid & 31;
    const int bwb  = blockIdx.x * BWSET;
    const int jb   = blockIdx.y * JCTA;

    // stage this CTA's W-bit words (coalesced)
    for (int i = tid; i < JCTA * 8; i += RK_THREADS)
        wbs[i] = wb[jb * 8 + i];

    // build LUT: warp w owns chunks w*4 .. w*4+3 (Gray-code incremental)
    #pragma unroll
    for (int cc = 0; cc < 4; ++cc) {
        int c = wid * 4 + cc;
        const uint32_t* sp = Sin + (size_t)(c * 4) * NBW + bwb + lane;
        uint32_t s0 = sp[0], s1 = sp[NBW], s2 = sp[2 * NBW], s3 = sp[3 * NBW];
        uint32_t* L = lut + c * (16 * 32) + lane;
        uint32_t t = 0;
        L[0 * 32] = t;
        t ^= s0; L[1 * 32] = t;   t ^= s1; L[3 * 32] = t;
        t ^= s0; L[2 * 32] = t;   t ^= s2; L[6 * 32] = t;
        t ^= s0; L[7 * 32] = t;   t ^= s1; L[5 * 32] = t;
        t ^= s0; L[4 * 32] = t;   t ^= s3; L[12 * 32] = t;
        t ^= s0; L[13 * 32] = t;  t ^= s1; L[15 * 32] = t;
        t ^= s0; L[14 * 32] = t;  t ^= s2; L[10 * 32] = t;
        t ^= s0; L[11 * 32] = t;  t ^= s1; L[9 * 32] = t;
        t ^= s0; L[8 * 32] = t;
    }
    __syncthreads();

    // each warp computes 8 output words (j columns) for its 32 bw lanes
    #pragma unroll 1
    for (int jj = 0; jj < 8; ++jj) {
        int jl = wid * 8 + jj;                // local j
        int j  = jb + jl;
        const uint32_t* wd = wbs + jl * 8;
        uint32_t acc0 = 0, acc1 = 0;          // two chains for ILP
        #pragma unroll
        for (int cw = 0; cw < 8; ++cw) {
            uint32_t wword = wd[cw];          // uniform LDS
            #pragma unroll
            for (int n = 0; n < 8; n += 2) {
                int c0 = cw * 8 + n, c1 = c0 + 1;
                uint32_t i0 = (wword >> (n * 4)) & 15u;
                uint32_t i1 = (wword >> (n * 4 + 4)) & 15u;
                acc0 ^= lut[(c0 * 16 + i0) * 32 + lane];
                acc1 ^= lut[(c1 * 16 + i1) * 32 + lane];
            }
        }
        uint32_t r = acc0 ^ acc1 ^ nmask[j];
        Sout[(size_t)j * NBW + bwb + lane] = r;
    }
}

// ---------------- unpack final bits to fp32 ----------------
__global__ void unpack_state(const uint32_t* __restrict__ S, float* __restrict__ out) {
    __shared__ uint32_t smw[HID];
    int bw = blockIdx.x;
    int tid = threadIdx.x;                    // 256 threads
    smw[tid] = S[(size_t)tid * NBW + bw];     // k = tid
    __syncthreads();
    int b  = tid >> 3;                        // row within group (0..31)
    int kq = (tid & 7) * 32;                  // 32 k per thread
    float* dst = out + ((size_t)bw * 32 + b) * HID + kq;
    #pragma unroll
    for (int q = 0; q < 8; ++q) {
        float4 v;
        v.x = (float)((smw[kq + q * 4 + 0] >> b) & 1u);
        v.y = (float)((smw[kq + q * 4 + 1] >> b) & 1u);
        v.z = (float)((smw[kq + q * 4 + 2] >> b) & 1u);
        v.w = (float)((smw[kq + q * 4 + 3] >> b) & 1u);
        reinterpret_cast<float4*>(dst)[q] = v;
    }
}

// ---------------- launch ----------------
extern "C" void kernel_launch(void* const* d_in, const int* in_sizes, int n_in,
                              void* d_out, int out_size) {
    const float* state    = (const float*)d_in[0];   // [65536, 256]
    const float* matrices = (const float*)d_in[1];   // [64, 256, 256]
    const float* noise    = (const float*)d_in[2];   // [64, 256]
    float* out = (float*)d_out;

    pack_W<<<(ROUNDS * HID * 8 + 255) / 256, 256>>>(matrices);
    pack_noise<<<(ROUNDS * HID + 255) / 256, 256>>>(noise);
    pack_state<<<(NBW * 32 + 255) / 256, 256>>>(state);

    static uint32_t* S0 = nullptr;
    uint32_t *s0, *s1;
    cudaGetSymbolAddress((void**)&s0, g_S);          // not an allocation
    s1 = s0 + (size_t)HID * NBW;
    uint32_t* wbp;
    cudaGetSymbolAddress((void**)&wbp, g_Wb);
    uint32_t* nmp;
    cudaGetSymbolAddress((void**)&nmp, g_nm);
    (void)S0;

    cudaFuncSetAttribute(round_gf2, cudaFuncAttributeMaxDynamicSharedMemorySize, RK_SMEM);

    dim3 grid(NBW / BWSET, JSPLIT);
    for (int r = 0; r < ROUNDS; ++r) {
        const uint32_t* in  = (r & 1) ? s1 : s0;
        uint32_t*       dst = (r & 1) ? s0 : s1;
        round_gf2<<<grid, RK_THREADS, RK_SMEM>>>(in, dst, wbp + (size_t)r * HID * 8,
                                                 nmp + (size_t)r * HID);
    }
    // after 64 rounds result is back in s0
    unpack_state<<<NBW, HID>>>(s0, out);
}

// round 10
// speedup vs baseline: 1.0150x; 1.0115x over previous
#include <cuda_runtime.h>
#include <cuda_bf16.h>
#include <cstdint>

#define ROUNDS 64
#define HID 256
#define BATCH 65536
#define NBW (BATCH / 32)            // 2048 packed batch words
#define BWSET 32                    // bw words per CTA (one per lane)
#define JSPLIT 2
#define JCTA (HID / JSPLIT)         // 128 j per CTA
#define RK_THREADS 512              // 16 warps

// ---------------- device-global scratch (no allocs allowed) ----------------
__device__ uint32_t g_S[2][HID * NBW];          // bit-sliced state [k][bw], ping-pong (2x2MB)
__device__ uint32_t g_Wb[ROUNDS * HID * 8];     // W bits: [r][j][8 words over k]
__device__ uint32_t g_nm[ROUNDS * HID];         // noise masks: 0 or 0xFFFFFFFF

// ---------------- prep: pack |W| bits ----------------
__global__ void pack_W(const float* __restrict__ W) {
    int w = blockIdx.x * blockDim.x + threadIdx.x;      // word index
    if (w >= ROUNDS * HID * 8) return;
    const float* src = W + (size_t)w * 32;              // 32 consecutive k of row (r,j)
    uint32_t bits = 0;
    #pragma unroll
    for (int q = 0; q < 8; ++q) {
        float4 v = reinterpret_cast<const float4*>(src)[q];
        bits |= (v.x != 0.f ? 1u : 0u) << (q * 4 + 0);
        bits |= (v.y != 0.f ? 1u : 0u) << (q * 4 + 1);
        bits |= (v.z != 0.f ? 1u : 0u) << (q * 4 + 2);
        bits |= (v.w != 0.f ? 1u : 0u) << (q * 4 + 3);
    }
    g_Wb[w] = bits;
}

// ---------------- prep: noise -> full masks ----------------
__global__ void pack_noise(const float* __restrict__ noise) {
    int i = blockIdx.x * blockDim.x + threadIdx.x;
    if (i < ROUNDS * HID) g_nm[i] = (noise[i] != 0.f) ? 0xFFFFFFFFu : 0u;
}

// ---------------- prep: bit-slice the state ----------------
// S[k][bw]: bit b = state[bw*32+b][k]
__global__ void pack_state(const float* __restrict__ state) {
    int warp = (blockIdx.x * blockDim.x + threadIdx.x) >> 5;  // one warp per bw
    int lane = threadIdx.x & 31;
    if (warp >= NBW) return;
    const float* base = state + (size_t)warp * 32 * HID;
    #pragma unroll
    for (int kc = 0; kc < 8; ++kc) {
        int k = kc * 32 + lane;
        uint32_t word = 0;
        #pragma unroll
        for (int b = 0; b < 32; ++b)
            word |= (base[(size_t)b * HID + k] != 0.f ? 1u : 0u) << b;
        g_S[0][(size_t)k * NBW + warp] = word;
    }
}

// ---------------- per-round GF(2) kernel ----------------
// grid (64, 2): x = bw-set (32 words), y = j-half (128 j)
// SMEM: LUT[64 chunks][16 entries][32 lanes] (128KB) + wb slice (4KB)
#define LUT_WORDS (64 * 16 * 32)
#define RK_SMEM (LUT_WORDS * 4 + JCTA * 8 * 4)

__global__ void __launch_bounds__(RK_THREADS, 1)
round_gf2(const uint32_t* __restrict__ Sin, uint32_t* __restrict__ Sout,
          const uint32_t* __restrict__ wb, const uint32_t* __restrict__ nmask) {
    extern __shared__ uint32_t sm[];
    uint32_t* lut = sm;                       // [c][e][lane]
    uint32_t* wbs = sm + LUT_WORDS;           // [JCTA][8]

    const int tid  = threadIdx.x;
    const int wid  = tid >> 5;
    const int lane = tid & 31;
    const int bwb  = blockIdx.x * BWSET;
    const int jb   = blockIdx.y * JCTA;

    // stage this CTA's W-bit words (coalesced)
    for (int i = tid; i < JCTA * 8; i += RK_THREADS)
        wbs[i] = wb[jb * 8 + i];

    // build LUT: warp w owns chunks w*4 .. w*4+3 (Gray-code incremental)
    #pragma unroll
    for (int cc = 0; cc < 4; ++cc) {
        int c = wid * 4 + cc;
        const uint32_t* sp = Sin + (size_t)(c * 4) * NBW + bwb + lane;
        uint32_t s0 = sp[0], s1 = sp[NBW], s2 = sp[2 * NBW], s3 = sp[3 * NBW];
        uint32_t* L = lut + c * (16 * 32) + lane;
        uint32_t t = 0;
        L[0 * 32] = t;
        t ^= s0; L[1 * 32] = t;   t ^= s1; L[3 * 32] = t;
        t ^= s0; L[2 * 32] = t;   t ^= s2; L[6 * 32] = t;
        t ^= s0; L[7 * 32] = t;   t ^= s1; L[5 * 32] = t;
        t ^= s0; L[4 * 32] = t;   t ^= s3; L[12 * 32] = t;
        t ^= s0; L[13 * 32] = t;  t ^= s1; L[15 * 32] = t;
        t ^= s0; L[14 * 32] = t;  t ^= s2; L[10 * 32] = t;
        t ^= s0; L[11 * 32] = t;  t ^= s1; L[9 * 32] = t;
        t ^= s0; L[8 * 32] = t;
    }
    __syncthreads();

    // each warp computes 8 output words (j columns) for its 32 bw lanes
    #pragma unroll 1
    for (int jj = 0; jj < 8; ++jj) {
        int jl = wid * 8 + jj;                // local j
        int j  = jb + jl;
        const uint32_t* wd = wbs + jl * 8;
        uint32_t acc0 = 0, acc1 = 0;          // two chains for ILP
        #pragma unroll
        for (int cw = 0; cw < 8; ++cw) {
            uint32_t wword = wd[cw];          // uniform LDS
            #pragma unroll
            for (int n = 0; n < 8; n += 2) {
                int c0 = cw * 8 + n, c1 = c0 + 1;
                uint32_t i0 = (wword >> (n * 4)) & 15u;
                uint32_t i1 = (wword >> (n * 4 + 4)) & 15u;
                acc0 ^= lut[(c0 * 16 + i0) * 32 + lane];
                acc1 ^= lut[(c1 * 16 + i1) * 32 + lane];
            }
        }
        uint32_t r = acc0 ^ acc1 ^ nmask[j];
        Sout[(size_t)j * NBW + bwb + lane] = r;
    }
}

// ---------------- unpack final bits to fp32 ----------------
__global__ void unpack_state(const uint32_t* __restrict__ S, float* __restrict__ out) {
    __shared__ uint32_t smw[HID];
    int bw = blockIdx.x;
    int tid = threadIdx.x;                    // 256 threads
    smw[tid] = S[(size_t)tid * NBW + bw];     // k = tid
    __syncthreads();
    int b  = tid >> 3;                        // row within group (0..31)
    int kq = (tid & 7) * 32;                  // 32 k per thread
    float* dst = out + ((size_t)bw * 32 + b) * HID + kq;
    #pragma unroll
    for (int q = 0; q < 8; ++q) {
        float4 v;
        v.x = (float)((smw[kq + q * 4 + 0] >> b) & 1u);
        v.y = (float)((smw[kq + q * 4 + 1] >> b) & 1u);
        v.z = (float)((smw[kq + q * 4 + 2] >> b) & 1u);
        v.w = (float)((smw[kq + q * 4 + 3] >> b) & 1u);
        reinterpret_cast<float4*>(dst)[q] = v;
    }
}

// ---------------- launch ----------------
extern "C" void kernel_launch(void* const* d_in, const int* in_sizes, int n_in,
                              void* d_out, int out_size) {
    const float* state    = (const float*)d_in[0];   // [65536, 256]
    const float* matrices = (const float*)d_in[1];   // [64, 256, 256]
    const float* noise    = (const float*)d_in[2];   // [64, 256]
    float* out = (float*)d_out;

    pack_W<<<(ROUNDS * HID * 8 + 255) / 256, 256>>>(matrices);
    pack_noise<<<(ROUNDS * HID + 255) / 256, 256>>>(noise);
    pack_state<<<(NBW * 32 + 255) / 256, 256>>>(state);

    static uint32_t* S0 = nullptr;
    uint32_t *s0, *s1;
    cudaGetSymbolAddress((void**)&s0, g_S);          // not an allocation
    s1 = s0 + (size_t)HID * NBW;
    uint32_t* wbp;
    cudaGetSymbolAddress((void**)&wbp, g_Wb);
    uint32_t* nmp;
    cudaGetSymbolAddress((void**)&nmp, g_nm);
    (void)S0;

    cudaFuncSetAttribute(round_gf2, cudaFuncAttributeMaxDynamicSharedMemorySize, RK_SMEM);

    dim3 grid(NBW / BWSET, JSPLIT);
    for (int r = 0; r < ROUNDS; ++r) {
        const uint32_t* in  = (r & 1) ? s1 : s0;
        uint32_t*       dst = (r & 1) ? s0 : s1;
        round_gf2<<<grid, RK_THREADS, RK_SMEM>>>(in, dst, wbp + (size_t)r * HID * 8,
                                                 nmp + (size_t)r * HID);
    }
    // after 64 rounds result is back in s0
    unpack_state<<<NBW, HID>>>(s0, out);
}